// round 1
// baseline (speedup 1.0000x reference)
#include <cuda_runtime.h>
#include <math.h>

// Problem constants (fixed by the dataset)
#define HID 2048
#define NEXP 256
#define NGRP 8
#define GSZ 32          // experts per group = 256/8
#define TOPG 4
#define TOPK 8
#define MAXTOK 16384
#define ROUTE_SCALE 2.5f

// scratch: pre-sigmoid linear scores (dot + bias), [N, 256]
__device__ float g_scores[MAXTOK * NEXP];

// ---------------------------------------------------------------------------
// GEMM: scores[m][e] = dot(x[m,:], w[e,:]) + bias[e]
// 128x128x16 tile, 256 threads, 8x8 microtile per thread, packed f32x2 FMA.
// ---------------------------------------------------------------------------
__global__ __launch_bounds__(256, 2)
void gate_gemm_kernel(const float* __restrict__ x,
                      const float* __restrict__ w,
                      const float* __restrict__ bias,
                      float* __restrict__ scores)
{
    __shared__ float xs[16][132];   // [k][m], padded
    __shared__ float ws[16][132];   // [k][e], padded

    const int tid = threadIdx.x;
    const int tx  = tid & 15;       // expert sub-tile
    const int ty  = tid >> 4;       // token  sub-tile
    const int m0  = blockIdx.y * 128;
    const int n0  = blockIdx.x * 128;

    const float* xbase = x + (size_t)m0 * HID;
    const float* wbase = w + (size_t)n0 * HID;

    unsigned long long acc[8][4];   // 8 rows x 4 f32x2 pairs (8 expert cols)
    #pragma unroll
    for (int i = 0; i < 8; i++)
        #pragma unroll
        for (int j = 0; j < 4; j++) acc[i][j] = 0ull;

    for (int k0 = 0; k0 < HID; k0 += 16) {
        // ---- load tiles: 128 rows x 16 k each, as float4 ----
        #pragma unroll
        for (int it = 0; it < 2; it++) {
            int id  = it * 256 + tid;
            int row = id >> 2;
            int kq  = (id & 3) * 4;
            float4 xv = *(const float4*)(xbase + (size_t)row * HID + k0 + kq);
            float4 wv = *(const float4*)(wbase + (size_t)row * HID + k0 + kq);
            xs[kq + 0][row] = xv.x; xs[kq + 1][row] = xv.y;
            xs[kq + 2][row] = xv.z; xs[kq + 3][row] = xv.w;
            ws[kq + 0][row] = wv.x; ws[kq + 1][row] = wv.y;
            ws[kq + 2][row] = wv.z; ws[kq + 3][row] = wv.w;
        }
        __syncthreads();

        // ---- compute ----
        #pragma unroll
        for (int kk = 0; kk < 16; kk++) {
            float4 A0 = *(const float4*)&xs[kk][ty * 8];
            float4 A1 = *(const float4*)&xs[kk][ty * 8 + 4];
            const unsigned long long* bp =
                (const unsigned long long*)&ws[kk][tx * 8];
            unsigned long long B0 = bp[0], B1 = bp[1], B2 = bp[2], B3 = bp[3];

            float a[8] = {A0.x, A0.y, A0.z, A0.w, A1.x, A1.y, A1.z, A1.w};
            #pragma unroll
            for (int i = 0; i < 8; i++) {
                unsigned long long aa;
                asm("mov.b64 %0, {%1, %1};" : "=l"(aa) : "f"(a[i]));
                asm("fma.rn.f32x2 %0, %1, %2, %0;" : "+l"(acc[i][0]) : "l"(aa), "l"(B0));
                asm("fma.rn.f32x2 %0, %1, %2, %0;" : "+l"(acc[i][1]) : "l"(aa), "l"(B1));
                asm("fma.rn.f32x2 %0, %1, %2, %0;" : "+l"(acc[i][2]) : "l"(aa), "l"(B2));
                asm("fma.rn.f32x2 %0, %1, %2, %0;" : "+l"(acc[i][3]) : "l"(aa), "l"(B3));
            }
        }
        __syncthreads();
    }

    // ---- epilogue: add bias, store ----
    float bb[8];
    #pragma unroll
    for (int j = 0; j < 8; j++) bb[j] = bias[n0 + tx * 8 + j];

    #pragma unroll
    for (int i = 0; i < 8; i++) {
        int m = m0 + ty * 8 + i;
        float v[8];
        #pragma unroll
        for (int j = 0; j < 4; j++) {
            float lo, hi;
            asm("mov.b64 {%0, %1}, %2;" : "=f"(lo), "=f"(hi) : "l"(acc[i][j]));
            v[2 * j]     = lo + bb[2 * j];
            v[2 * j + 1] = hi + bb[2 * j + 1];
        }
        float4* outp = (float4*)&scores[(size_t)m * NEXP + n0 + tx * 8];
        outp[0] = make_float4(v[0], v[1], v[2], v[3]);
        outp[1] = make_float4(v[4], v[5], v[6], v[7]);
    }
}

// ---------------------------------------------------------------------------
// Routing: one warp per token. Lane l holds experts e = s*32 + l, s = group.
// ---------------------------------------------------------------------------
__global__ void gate_route_kernel(const float* __restrict__ scores,
                                  const float* __restrict__ bias,
                                  float* __restrict__ out,
                                  int N, int with_idx)
{
    const int token = blockIdx.x * 8 + (threadIdx.x >> 5);
    const int lane  = threadIdx.x & 31;
    if (token >= N) return;

    const float* row = scores + (size_t)token * NEXP;

    float orig[NGRP];   // sigmoid(lin)
    float rsc[NGRP];    // sigmoid(lin) + bias  (routing score)
    #pragma unroll
    for (int s = 0; s < NGRP; s++) {
        int e = s * 32 + lane;
        float lin = row[e];                 // already includes +bias pre-sigmoid
        float sg  = 1.0f / (1.0f + expf(-lin));
        orig[s] = sg;
        rsc[s]  = sg + bias[e];
    }

    // group score = sum of top-2 routing scores in the group (32 lanes)
    float gs[NGRP];
    #pragma unroll
    for (int g = 0; g < NGRP; g++) {
        float m1 = rsc[g];
        int   l1 = lane;
        #pragma unroll
        for (int off = 16; off >= 1; off >>= 1) {
            float ov = __shfl_xor_sync(0xffffffffu, m1, off);
            int   ol = __shfl_xor_sync(0xffffffffu, l1, off);
            if (ov > m1 || (ov == m1 && ol < l1)) { m1 = ov; l1 = ol; }
        }
        float v2 = (lane == l1) ? -INFINITY : rsc[g];
        #pragma unroll
        for (int off = 16; off >= 1; off >>= 1)
            v2 = fmaxf(v2, __shfl_xor_sync(0xffffffffu, v2, off));
        gs[g] = m1 + v2;  // identical on all lanes
    }

    // keep top-4 groups (ties -> lower group index)
    bool keep[NGRP];
    #pragma unroll
    for (int g = 0; g < NGRP; g++) {
        int cnt = 0;
        #pragma unroll
        for (int h = 0; h < NGRP; h++)
            cnt += (gs[h] > gs[g]) || (gs[h] == gs[g] && h < g);
        keep[g] = (cnt < TOPG);
    }

    float mv[NGRP];
    #pragma unroll
    for (int s = 0; s < NGRP; s++) mv[s] = keep[s] ? rsc[s] : -INFINITY;

    // iterative top-8 over masked routing scores (ties -> lower expert index)
    float wsel[TOPK];
    int   esel[TOPK];
    #pragma unroll
    for (int it = 0; it < TOPK; it++) {
        float bv = -INFINITY; int be = NEXP; float bo = 0.0f;
        #pragma unroll
        for (int s = 0; s < NGRP; s++) {
            if (mv[s] > bv) { bv = mv[s]; be = s * 32 + lane; bo = orig[s]; }
        }
        #pragma unroll
        for (int off = 16; off >= 1; off >>= 1) {
            float ov = __shfl_xor_sync(0xffffffffu, bv, off);
            int   oe = __shfl_xor_sync(0xffffffffu, be, off);
            float oo = __shfl_xor_sync(0xffffffffu, bo, off);
            if (ov > bv || (ov == bv && oe < be)) { bv = ov; be = oe; bo = oo; }
        }
        wsel[it] = bo;
        esel[it] = be;
        if ((be & 31) == lane) {
            int bslot = be >> 5;
            #pragma unroll
            for (int s = 0; s < NGRP; s++)
                if (s == bslot) mv[s] = -INFINITY;
        }
    }

    float tot = 0.0f;
    #pragma unroll
    for (int it = 0; it < TOPK; it++) tot += wsel[it];
    float inv = ROUTE_SCALE / tot;

    #pragma unroll
    for (int it = 0; it < TOPK; it++) {
        if (lane == it) {
            out[(size_t)token * TOPK + it] = wsel[it] * inv;
            if (with_idx)
                out[(size_t)N * TOPK + (size_t)token * TOPK + it] =
                    (float)esel[it];
        }
    }
}

// ---------------------------------------------------------------------------
extern "C" void kernel_launch(void* const* d_in, const int* in_sizes, int n_in,
                              void* d_out, int out_size)
{
    const float* x    = (const float*)d_in[0];
    const float* w    = (const float*)d_in[1];
    const float* bias = (const float*)d_in[2];
    float* out = (float*)d_out;

    int N = in_sizes[0] / HID;
    if (N > MAXTOK) N = MAXTOK;

    float* scores = nullptr;
    cudaGetSymbolAddress((void**)&scores, g_scores);

    dim3 ggrid(NEXP / 128, N / 128);
    gate_gemm_kernel<<<ggrid, 256>>>(x, w, bias, scores);

    int with_idx = (out_size >= 2 * N * TOPK) ? 1 : 0;
    gate_route_kernel<<<(N + 7) / 8, 256>>>(scores, bias, out, N, with_idx);
}

// round 3
// speedup vs baseline: 1.3513x; 1.3513x over previous
#include <cuda_runtime.h>
#include <math.h>
#include <stdint.h>

// ---------------- problem constants ----------------
#define HID 2048
#define NEXP 256
#define NGRP 8
#define TOPG 4
#define TOPK 8
#define RSCALE 2.5f
#define MT 128                 // tokens per CTA
#define KT 32                  // K per smem stage
#define NST (HID / KT)         // 64 stages

// ---------------- smem layout ----------------
// row stride 36 floats (144B): bank = (4*row + k) & 31 -> conflict-free
#define RS 36
#define OFF_BIAS 0
#define OFF_TILES 1024
#define A_HI 0
#define A_LO (MT * RS * 4)                   // 18432
#define B_HI (2 * MT * RS * 4)               // 36864
#define B_LO (2 * MT * RS * 4 + NEXP * RS * 4)
#define STAGE (2 * MT * RS * 4 + 2 * NEXP * RS * 4)   // 110592
#define SMEM_TOTAL (OFF_TILES + 2 * STAGE)            // 222208
#define SC_STRIDE 260          // scores overlay row stride (floats)

#define MMA(d, a, b) asm volatile( \
    "mma.sync.aligned.m16n8k8.row.col.f32.tf32.tf32.f32 " \
    "{%0,%1,%2,%3},{%4,%5,%6,%7},{%8,%9},{%0,%1,%2,%3};" \
    : "+f"((d)[0]), "+f"((d)[1]), "+f"((d)[2]), "+f"((d)[3]) \
    : "r"((a)[0]), "r"((a)[1]), "r"((a)[2]), "r"((a)[3]), \
      "r"((b)[0]), "r"((b)[1]))

static __device__ __forceinline__ void split2(float v, uint32_t& h, uint32_t& l) {
    uint32_t b = __float_as_uint(v);
    h = b & 0xFFFFE000u;                       // tf32 hi (truncate 13 LSBs)
    l = __float_as_uint(v - __uint_as_float(h)); // exact residual; HMMA truncates it
}

static __device__ __forceinline__ float sigm(float x) {
    return __fdividef(1.0f, 1.0f + __expf(-x));
}

// ---------------------------------------------------------------------------
// Fused: 3xTF32 mma.sync scoring GEMM (128 x 256 x 2048 per CTA) + sigmoid +
// grouped top-k routing. One CTA per 128 tokens, 8 warps, 64x64 warp tiles.
// ---------------------------------------------------------------------------
extern "C" __global__ void __launch_bounds__(256, 1)
gate_fused_kernel(const float* __restrict__ x,
                  const float* __restrict__ w,
                  const float* __restrict__ bias,
                  float* __restrict__ out, int N, int with_idx)
{
    extern __shared__ __align__(1024) char smem[];
    const int tid  = threadIdx.x;
    const int wid  = tid >> 5;
    const int lane = tid & 31;
    const int m0   = blockIdx.x * MT;
    const int wm   = wid & 1;      // 2 M-groups of 64
    const int wn   = wid >> 1;     // 4 N-groups of 64

    float* bs = (float*)(smem + OFF_BIAS);
    if (tid < NEXP) bs[tid] = bias[tid];

    float acc[4][8][4];
    #pragma unroll
    for (int i = 0; i < 4; i++)
        #pragma unroll
        for (int j = 0; j < 8; j++)
            #pragma unroll
            for (int c = 0; c < 4; c++) acc[i][j][c] = 0.0f;

    const int arow = tid >> 3;          // gmem A row (0..127 over 2 passes? no: see below)
    const int aq   = tid & 7;

    float4 av[4], bv[8];

    // ---- load global tile for stage s into regs ----
    auto ldg = [&](int s) {
        const int k0 = s * KT;
        #pragma unroll
        for (int i = 0; i < 4; i++) {
            int id = tid + i * 256, row = id >> 3, q = id & 7;
            av[i] = *(const float4*)(x + (size_t)(m0 + row) * HID + k0 + q * 4);
        }
        #pragma unroll
        for (int i = 0; i < 8; i++) {
            int id = tid + i * 256, row = id >> 3, q = id & 7;
            bv[i] = *(const float4*)(w + (size_t)row * HID + k0 + q * 4);
        }
    };

    // ---- split regs -> smem stage buffer ----
    auto sts = [&](int s) {
        char* buf = smem + OFF_TILES + (s & 1) * STAGE;
        #pragma unroll
        for (int i = 0; i < 4; i++) {
            int id = tid + i * 256, row = id >> 3, q = id & 7;
            uint4 h, l;
            split2(av[i].x, h.x, l.x); split2(av[i].y, h.y, l.y);
            split2(av[i].z, h.z, l.z); split2(av[i].w, h.w, l.w);
            uint32_t o = (uint32_t)(row * (RS * 4) + q * 16);
            *(uint4*)(buf + A_HI + o) = h;
            *(uint4*)(buf + A_LO + o) = l;
        }
        #pragma unroll
        for (int i = 0; i < 8; i++) {
            int id = tid + i * 256, row = id >> 3, q = id & 7;
            uint4 h, l;
            split2(bv[i].x, h.x, l.x); split2(bv[i].y, h.y, l.y);
            split2(bv[i].z, h.z, l.z); split2(bv[i].w, h.w, l.w);
            uint32_t o = (uint32_t)(row * (RS * 4) + q * 16);
            *(uint4*)(buf + B_HI + o) = h;
            *(uint4*)(buf + B_LO + o) = l;
        }
    };

    // frag base offsets (in floats)
    const int afo = (wm * 64 + (lane >> 2)) * RS + (lane & 3);
    const int bfo = (wn * 64 + (lane >> 2)) * RS + (lane & 3);

    auto compute = [&](int s) {
        const char* buf = smem + OFF_TILES + (s & 1) * STAGE;
        const uint32_t* Ah = (const uint32_t*)(buf + A_HI);
        const uint32_t* Al = (const uint32_t*)(buf + A_LO);
        const uint32_t* Bh = (const uint32_t*)(buf + B_HI);
        const uint32_t* Bl = (const uint32_t*)(buf + B_LO);
        #pragma unroll
        for (int ks = 0; ks < 4; ks++) {
            const int kb = ks * 8;
            uint32_t ah[4][4], al[4][4], bh[8][2];
            #pragma unroll
            for (int mi = 0; mi < 4; mi++) {
                int o = afo + mi * (16 * RS) + kb;
                ah[mi][0] = Ah[o];            ah[mi][1] = Ah[o + 8 * RS];
                ah[mi][2] = Ah[o + 4];        ah[mi][3] = Ah[o + 8 * RS + 4];
                al[mi][0] = Al[o];            al[mi][1] = Al[o + 8 * RS];
                al[mi][2] = Al[o + 4];        al[mi][3] = Al[o + 8 * RS + 4];
            }
            #pragma unroll
            for (int ni = 0; ni < 8; ni++) {
                int o = bfo + ni * (8 * RS) + kb;
                bh[ni][0] = Bh[o]; bh[ni][1] = Bh[o + 4];
            }
            #pragma unroll
            for (int mi = 0; mi < 4; mi++)
                #pragma unroll
                for (int ni = 0; ni < 8; ni++) MMA(acc[mi][ni], ah[mi], bh[ni]);
            #pragma unroll
            for (int mi = 0; mi < 4; mi++)
                #pragma unroll
                for (int ni = 0; ni < 8; ni++) MMA(acc[mi][ni], al[mi], bh[ni]);
            uint32_t bl[8][2];
            #pragma unroll
            for (int ni = 0; ni < 8; ni++) {
                int o = bfo + ni * (8 * RS) + kb;
                bl[ni][0] = Bl[o]; bl[ni][1] = Bl[o + 4];
            }
            #pragma unroll
            for (int mi = 0; mi < 4; mi++)
                #pragma unroll
                for (int ni = 0; ni < 8; ni++) MMA(acc[mi][ni], ah[mi], bl[ni]);
        }
    };

    // ---- pipelined main loop ----
    ldg(0); sts(0);
    for (int s = 0; s < NST; s++) {
        __syncthreads();
        if (s + 1 < NST) ldg(s + 1);
        compute(s);
        if (s + 1 < NST) sts(s + 1);
    }
    __syncthreads();   // all compute done; tile smem free for scores overlay

    // ---- epilogue: +bias, sigmoid, write scores overlay ----
    float* sc = (float*)(smem + OFF_TILES);
    #pragma unroll
    for (int mi = 0; mi < 4; mi++) {
        int tr = wm * 64 + mi * 16 + (lane >> 2);
        #pragma unroll
        for (int ni = 0; ni < 8; ni++) {
            int e = wn * 64 + ni * 8 + (lane & 3) * 2;
            float2 v0, v1;
            v0.x = sigm(acc[mi][ni][0] + bs[e]);
            v0.y = sigm(acc[mi][ni][1] + bs[e + 1]);
            v1.x = sigm(acc[mi][ni][2] + bs[e]);
            v1.y = sigm(acc[mi][ni][3] + bs[e + 1]);
            *(float2*)&sc[tr * SC_STRIDE + e]       = v0;
            *(float2*)&sc[(tr + 8) * SC_STRIDE + e] = v1;
        }
    }
    __syncthreads();

    // ---- routing: warp per token, 16 tokens per warp ----
    for (int it = 0; it < 16; it++) {
        const int t = wid * 16 + it;
        const float* row = sc + t * SC_STRIDE;

        float orig[NGRP], rsc[NGRP];
        #pragma unroll
        for (int s = 0; s < NGRP; s++) {
            float sg = row[s * 32 + lane];
            orig[s] = sg;
            rsc[s] = sg + bs[s * 32 + lane];
        }

        // group score = top-2 sum (ties -> lower expert index)
        float gs[NGRP];
        #pragma unroll
        for (int g = 0; g < NGRP; g++) {
            float m1 = rsc[g];
            int l1 = lane;
            #pragma unroll
            for (int off = 16; off >= 1; off >>= 1) {
                float ov = __shfl_xor_sync(0xffffffffu, m1, off);
                int ol = __shfl_xor_sync(0xffffffffu, l1, off);
                if (ov > m1 || (ov == m1 && ol < l1)) { m1 = ov; l1 = ol; }
            }
            float v2 = (lane == l1) ? -INFINITY : rsc[g];
            #pragma unroll
            for (int off = 16; off >= 1; off >>= 1)
                v2 = fmaxf(v2, __shfl_xor_sync(0xffffffffu, v2, off));
            gs[g] = m1 + v2;
        }

        // keep top-4 groups (ties -> lower group index)
        float mv[NGRP];
        #pragma unroll
        for (int g = 0; g < NGRP; g++) {
            int cnt = 0;
            #pragma unroll
            for (int h = 0; h < NGRP; h++)
                cnt += (gs[h] > gs[g]) || (gs[h] == gs[g] && h < g);
            mv[g] = (cnt < TOPG) ? rsc[g] : -INFINITY;
        }

        // iterative top-8 (ties -> lower expert index)
        float wsel[TOPK];
        int esel[TOPK];
        #pragma unroll
        for (int k = 0; k < TOPK; k++) {
            float bv2 = -INFINITY; int be = NEXP; float bo = 0.0f;
            #pragma unroll
            for (int s = 0; s < NGRP; s++)
                if (mv[s] > bv2) { bv2 = mv[s]; be = s * 32 + lane; bo = orig[s]; }
            #pragma unroll
            for (int off = 16; off >= 1; off >>= 1) {
                float ov = __shfl_xor_sync(0xffffffffu, bv2, off);
                int oe = __shfl_xor_sync(0xffffffffu, be, off);
                float oo = __shfl_xor_sync(0xffffffffu, bo, off);
                if (ov > bv2 || (ov == bv2 && oe < be)) { bv2 = ov; be = oe; bo = oo; }
            }
            wsel[k] = bo;
            esel[k] = be;
            if ((be & 31) == lane) {
                int bslot = be >> 5;
                #pragma unroll
                for (int s = 0; s < NGRP; s++)
                    if (s == bslot) mv[s] = -INFINITY;
            }
        }

        float tot = 0.0f;
        #pragma unroll
        for (int k = 0; k < TOPK; k++) tot += wsel[k];
        float inv = RSCALE / tot;

        const int gt = m0 + t;
        #pragma unroll
        for (int k = 0; k < TOPK; k++) {
            if (lane == k) {
                out[(size_t)gt * TOPK + k] = wsel[k] * inv;
                if (with_idx)
                    out[(size_t)N * TOPK + (size_t)gt * TOPK + k] = (float)esel[k];
            }
        }
    }
}

// ---------------------------------------------------------------------------
extern "C" void kernel_launch(void* const* d_in, const int* in_sizes, int n_in,
                              void* d_out, int out_size)
{
    const float* x    = (const float*)d_in[0];
    const float* w    = (const float*)d_in[1];
    const float* bias = (const float*)d_in[2];
    float* out = (float*)d_out;

    int N = in_sizes[0] / HID;
    int with_idx = (out_size >= 2 * N * TOPK) ? 1 : 0;

    cudaFuncSetAttribute(gate_fused_kernel,
                         cudaFuncAttributeMaxDynamicSharedMemorySize, SMEM_TOTAL);
    gate_fused_kernel<<<N / MT, 256, SMEM_TOTAL>>>(x, w, bias, out, N, with_idx);
}